// round 5
// baseline (speedup 1.0000x reference)
#include <cuda_runtime.h>
#include <cstddef>

#define BATCH 512
#define TT    512
#define DD    128
#define DOUTN 32
#define CCLS  4

#define ALPHA_C 0.1f
#define GAMMA_C 0.9f
#define EPS_C   1e-5f
#define EPSH_C  1e-6f
#define LNEPS_C 1e-5f

__device__ __forceinline__ float warp_sum(float v) {
#pragma unroll
    for (int s = 16; s > 0; s >>= 1)
        v += __shfl_xor_sync(0xffffffffu, v, s, 32);
    return v;
}

__device__ __forceinline__ unsigned long long fma2(unsigned long long a,
                                                   unsigned long long b,
                                                   unsigned long long c) {
    unsigned long long d;
    asm("fma.rn.f32x2 %0, %1, %2, %3;" : "=l"(d) : "l"(a), "l"(b), "l"(c));
    return d;
}

__device__ __forceinline__ unsigned long long add2(unsigned long long a,
                                                   unsigned long long b) {
    unsigned long long d;
    asm("add.rn.f32x2 %0, %1, %2;" : "=l"(d) : "l"(a), "l"(b));
    return d;
}

__device__ __forceinline__ unsigned long long pack2(float lo, float hi) {
    unsigned long long r;
    asm("mov.b64 %0, {%1, %2};" : "=l"(r) : "f"(lo), "f"(hi));
    return r;
}

__device__ __forceinline__ void unpack2(unsigned long long v, float& lo, float& hi) {
    asm("mov.b64 {%0, %1}, %2;" : "=f"(lo), "=f"(hi) : "l"(v));
}

// Packed 6-value warp reduction used for the final (post-loop) epilogue.
__device__ __forceinline__ float packed_reduce6(float px, float px2,
                                                float pd0, float pd1,
                                                float pd2, float pd3,
                                                int lane) {
    px  += __shfl_xor_sync(0xffffffffu, px,  16, 32);
    px2 += __shfl_xor_sync(0xffffffffu, px2, 16, 32);
    pd0 += __shfl_xor_sync(0xffffffffu, pd0, 16, 32);
    pd1 += __shfl_xor_sync(0xffffffffu, pd1, 16, 32);
    pd2 += __shfl_xor_sync(0xffffffffu, pd2, 16, 32);
    pd3 += __shfl_xor_sync(0xffffffffu, pd3, 16, 32);
    const bool hi16 = (lane & 16) != 0;
    float pA = hi16 ? px2 : px;
    float pB = hi16 ? pd1 : pd0;
    float pC = hi16 ? pd3 : pd2;
    pA += __shfl_xor_sync(0xffffffffu, pA, 8, 32);
    pB += __shfl_xor_sync(0xffffffffu, pB, 8, 32);
    pC += __shfl_xor_sync(0xffffffffu, pC, 8, 32);
    pA += __shfl_xor_sync(0xffffffffu, pA, 4, 32);
    pB += __shfl_xor_sync(0xffffffffu, pB, 4, 32);
    pC += __shfl_xor_sync(0xffffffffu, pC, 4, 32);
    float u = (lane & 8) ? ((lane & 4) ? 0.0f : pC)
                         : ((lane & 4) ? pB : pA);
    u += __shfl_xor_sync(0xffffffffu, u, 2, 32);
    u += __shfl_xor_sync(0xffffffffu, u, 1, 32);
    return u;
}

__global__ __launch_bounds__(128, 1)
void sync_head_kernel(const float* __restrict__ z_ticks,
                      const float* __restrict__ proj,
                      const float* __restrict__ ln_w,
                      const float* __restrict__ ln_b,
                      const float* __restrict__ cls_w,
                      const float* __restrict__ cls_b,
                      float* __restrict__ out_x,
                      float* __restrict__ out_logits) {
    __shared__ __align__(16) float sZ[2][4][DD];
    __shared__ float4 cst[TT];      // (unused, alpha*inv_denom/128, (1-alpha)*inv_denom, inv_s)
    __shared__ float itab[TT + 1];  // inv_tau(t) = 1/(t+1), index 0..TT

    const int lane  = threadIdx.x & 31;
    const int w     = threadIdx.x >> 5;
    const int batch = blockIdx.x * 4 + w;

    // ---- per-t constant tables (parallel fill; pure functions of t) ----
    for (int t = threadIdx.x; t <= TT; t += 128) {
        float tau = (float)(t + 1);
        itab[t] = 1.0f / tau;
        if (t < TT) {
            float denom = fmaxf(tau - 1.0f, 1.0f);
            float inv_denom = 1.0f / denom;
            float g = __powf(GAMMA_C, tau);
            float s = (1.0f - g) / (1.0f - GAMMA_C);
            cst[t] = make_float4(0.0f,
                                 ALPHA_C * inv_denom * (1.0f / 128.0f),
                                 (1.0f - ALPHA_C) * inv_denom,
                                 1.0f / s);
        }
    }

    // ---- proj column `lane` in registers, packed for f32x2 FMA ----
    unsigned long long q[DD / 2];
#pragma unroll
    for (int i = 0; i < DD / 2; i++) {
        float a = proj[(2 * i) * DOUTN + lane];
        float b = proj[(2 * i + 1) * DOUTN + lane];
        q[i] = pack2(a, b);
    }

    // ---- fold LayerNorm affine + classifier into per-lane constants ----
    const float lw = ln_w[lane];
    const float lb = ln_b[lane];
    const float w0 = cls_w[0 * DOUTN + lane];
    const float w1 = cls_w[1 * DOUTN + lane];
    const float w2 = cls_w[2 * DOUTN + lane];
    const float w3 = cls_w[3 * DOUTN + lane];
    const float a0 = lw * w0, a1 = lw * w1, a2 = lw * w2, a3 = lw * w3;
    const float Sa0 = warp_sum(a0);
    const float Sa1 = warp_sum(a1);
    const float Sa2 = warp_sum(a2);
    const float Sa3 = warp_sum(a3);
    const float Sb0 = warp_sum(lb * w0) + cls_b[0];
    const float Sb1 = warp_sum(lb * w1) + cls_b[1];
    const float Sb2 = warp_sum(lb * w2) + cls_b[2];
    const float Sb3 = warp_sum(lb * w3) + cls_b[3];
    const float Sa_l = (lane == 0) ? Sa0 : (lane == 1) ? Sa1 : (lane == 2) ? Sa2 : Sa3;
    const float Sb_l = (lane == 0) ? Sb0 : (lane == 1) ? Sb1 : (lane == 2) ? Sb2 : Sb3;
    const int dsrc = ((lane & 1) << 4) | ((lane & 2) ? 8 : 4);

    __syncthreads();   // tables ready

    const float* zptr = z_ticks + (size_t)batch * TT * DD + lane * 4;
    float* ox  = out_x + ((size_t)batch * TT) * DOUTN + lane;
    float* olb = out_logits + ((size_t)batch * TT) * CCLS + lane;

    // ---- preamble: absorb step 0's Welford (m = z0, e = 0, s = 0, b = 0) ----
    float4 z0 = *(const float4*)(zptr);
    float m0 = z0.x, m1 = z0.y, m2_ = z0.z, m3 = z0.w;
    float s0 = 0.f, s1 = 0.f, s2 = 0.f, s3 = 0.f;
    float e0 = 0.f, e1 = 0.f, e2 = 0.f, e3 = 0.f;
    float b = 0.f;                     // reduced msum for current step
    float h = 0.f;
    float px = 0.f, px2 = 0.f, pd0 = 0.f, pd1 = 0.f, pd2 = 0.f, pd3 = 0.f;

    float4 zb0 = *(const float4*)(zptr + DD);        // z_{t+1}
    float4 zb1 = *(const float4*)(zptr + 2 * DD);    // z_{t+2}

#pragma unroll 1
    for (int t = 0; t < TT; t++) {
        const float4 C = cst[t];

        // ---- z_tilde for step t (state e, s, b is for step t) ----
        const float c2 = fmaf(b, C.y, EPS_C);
        const float zt0 = e0 * rsqrtf(fmaf(s0, C.z, c2));
        const float zt1 = e1 * rsqrtf(fmaf(s1, C.z, c2));
        const float zt2 = e2 * rsqrtf(fmaf(s2, C.z, c2));
        const float zt3 = e3 * rsqrtf(fmaf(s3, C.z, c2));

        float* sb = sZ[t & 1][w];
        ((float4*)sb)[lane] = make_float4(zt0, zt1, zt2, zt3);
        __syncwarp();

        // ---- Welford for step t+1 (independent of this step's matvec) ----
        const float4 z = zb0;
        zb0 = zb1;
        {
            int tp = t + 3; if (tp > TT - 1) tp = TT - 1;
            zb1 = *(const float4*)(zptr + (size_t)tp * DD);
        }
        const float itn = itab[t + 1];
        float d0 = z.x - m0, d1 = z.y - m1, d2 = z.z - m2_, d3 = z.w - m3;
        m0 = fmaf(d0, itn, m0);
        m1 = fmaf(d1, itn, m1);
        m2_ = fmaf(d2, itn, m2_);
        m3 = fmaf(d3, itn, m3);
        e0 = z.x - m0; e1 = z.y - m1; e2 = z.z - m2_; e3 = z.w - m3;
        s0 = fmaf(d0, e0, s0);
        s1 = fmaf(d1, e1, s1);
        s2 = fmaf(d2, e2, s2);
        s3 = fmaf(d3, e3, s3);
        float bn = (s0 + s1) + (s2 + s3);   // msum for step t+1

        // ---- matvec for step t, manually interleaved with:
        //        * butterfly for bn        (consumed NEXT iteration)
        //        * packed reduce of x_{t-1} epilogue (consumed end of THIS iter)
        const ulonglong2* zp = (const ulonglong2*)sb;
        unsigned long long acc0 = 0ull, acc1 = 0ull, acc2 = 0ull, acc3 = 0ull;

#define MV_CHUNK(c)                                      \
        {   ulonglong2 za = zp[2 * (c)];                 \
            ulonglong2 zc = zp[2 * (c) + 1];             \
            acc0 = fma2(za.x, q[4 * (c) + 0], acc0);     \
            acc1 = fma2(za.y, q[4 * (c) + 1], acc1);     \
            acc2 = fma2(zc.x, q[4 * (c) + 2], acc2);     \
            acc3 = fma2(zc.y, q[4 * (c) + 3], acc3);  }

        MV_CHUNK(0)
        bn  += __shfl_xor_sync(0xffffffffu, bn,  16, 32);
        px  += __shfl_xor_sync(0xffffffffu, px,  16, 32);
        px2 += __shfl_xor_sync(0xffffffffu, px2, 16, 32);
        MV_CHUNK(1)
        pd0 += __shfl_xor_sync(0xffffffffu, pd0, 16, 32);
        pd1 += __shfl_xor_sync(0xffffffffu, pd1, 16, 32);
        pd2 += __shfl_xor_sync(0xffffffffu, pd2, 16, 32);
        pd3 += __shfl_xor_sync(0xffffffffu, pd3, 16, 32);
        MV_CHUNK(2)
        MV_CHUNK(3)
        const bool hi16 = (lane & 16) != 0;
        float pA = hi16 ? px2 : px;
        float pB = hi16 ? pd1 : pd0;
        float pC = hi16 ? pd3 : pd2;
        bn += __shfl_xor_sync(0xffffffffu, bn, 8, 32);
        pA += __shfl_xor_sync(0xffffffffu, pA, 8, 32);
        MV_CHUNK(4)
        pB += __shfl_xor_sync(0xffffffffu, pB, 8, 32);
        pC += __shfl_xor_sync(0xffffffffu, pC, 8, 32);
        MV_CHUNK(5)
        MV_CHUNK(6)
        bn += __shfl_xor_sync(0xffffffffu, bn, 4, 32);
        pA += __shfl_xor_sync(0xffffffffu, pA, 4, 32);
        MV_CHUNK(7)
        pB += __shfl_xor_sync(0xffffffffu, pB, 4, 32);
        pC += __shfl_xor_sync(0xffffffffu, pC, 4, 32);
        MV_CHUNK(8)
        MV_CHUNK(9)
        float u = (lane & 8) ? ((lane & 4) ? 0.0f : pC)
                             : ((lane & 4) ? pB : pA);
        bn += __shfl_xor_sync(0xffffffffu, bn, 2, 32);
        u  += __shfl_xor_sync(0xffffffffu, u,  2, 32);
        MV_CHUNK(10)
        MV_CHUNK(11)
        bn += __shfl_xor_sync(0xffffffffu, bn, 1, 32);
        u  += __shfl_xor_sync(0xffffffffu, u,  1, 32);
        MV_CHUNK(12)
        MV_CHUNK(13)
        const float sx2v = __shfl_sync(0xffffffffu, u, 16, 32);
        const float dotv = __shfl_sync(0xffffffffu, u, dsrc, 32);
        MV_CHUNK(14)
        MV_CHUNK(15)
#undef MV_CHUNK

        b = bn;   // reduced msum for step t+1

        // ---- r = horizontal sum of accumulators (pairwise f32x2) ----
        unsigned long long sAB = add2(acc0, acc1);
        unsigned long long sCD = add2(acc2, acc3);
        unsigned long long sT  = add2(sAB, sCD);
        float rlo, rhi;
        unpack2(sT, rlo, rhi);
        const float r = rlo + rhi;

        // ---- h EMA, log feature ----
        h = fmaf(r, r, GAMMA_C * h);
        const float xv = __logf(fmaf(h, C.w, EPSH_C));
        ox[(size_t)t * DOUTN] = xv;

        // ---- logits for step t-1 (reduction results just computed) ----
        if (t > 0 && lane < CCLS) {
            const float mu      = u * (1.0f / 32.0f);
            const float var     = fmaf(sx2v, 1.0f / 32.0f, -mu * mu);
            const float inv_std = rsqrtf(var + LNEPS_C);
            olb[(size_t)(t - 1) * CCLS] = fmaf(inv_std, fmaf(-mu, Sa_l, dotv), Sb_l);
        }

        // ---- queue epilogue values for next iteration ----
        px  = xv;
        px2 = xv * xv;
        pd0 = xv * a0;
        pd1 = xv * a1;
        pd2 = xv * a2;
        pd3 = xv * a3;
    }

    // ---- final epilogue for t = TT-1 ----
    {
        const float u = packed_reduce6(px, px2, pd0, pd1, pd2, pd3, lane);
        const float sx2v = __shfl_sync(0xffffffffu, u, 16, 32);
        const float dotv = __shfl_sync(0xffffffffu, u, dsrc, 32);
        if (lane < CCLS) {
            const float mu      = u * (1.0f / 32.0f);
            const float var     = fmaf(sx2v, 1.0f / 32.0f, -mu * mu);
            const float inv_std = rsqrtf(var + LNEPS_C);
            olb[(size_t)(TT - 1) * CCLS] = fmaf(inv_std, fmaf(-mu, Sa_l, dotv), Sb_l);
        }
    }
}

extern "C" void kernel_launch(void* const* d_in, const int* in_sizes, int n_in,
                              void* d_out, int out_size) {
    const float* z_ticks = (const float*)d_in[0];
    const float* proj    = (const float*)d_in[1];
    const float* ln_w    = (const float*)d_in[2];
    const float* ln_b    = (const float*)d_in[3];
    const float* cls_w   = (const float*)d_in[4];
    const float* cls_b   = (const float*)d_in[5];

    float* out_x      = (float*)d_out;
    float* out_logits = out_x + (size_t)BATCH * TT * DOUTN;

    sync_head_kernel<<<BATCH / 4, 128>>>(z_ticks, proj, ln_w, ln_b,
                                         cls_w, cls_b, out_x, out_logits);
}

// round 7
// speedup vs baseline: 1.0937x; 1.0937x over previous
#include <cuda_runtime.h>
#include <cstddef>

#define BATCH 512
#define TT    512
#define DD    128
#define DOUTN 32
#define CCLS  4
#define TBLK  32            // deferred-epilogue batch size
#define XPITCH 33           // xbuf pitch (bank-conflict-free)

#define ALPHA_C 0.1f
#define GAMMA_C 0.9f
#define EPS_C   1e-5f
#define EPSH_C  1e-6f
#define LNEPS_C 1e-5f

__device__ __forceinline__ float warp_sum(float v) {
#pragma unroll
    for (int s = 16; s > 0; s >>= 1)
        v += __shfl_xor_sync(0xffffffffu, v, s, 32);
    return v;
}

__device__ __forceinline__ unsigned long long fma2(unsigned long long a,
                                                   unsigned long long b,
                                                   unsigned long long c) {
    unsigned long long d;
    asm("fma.rn.f32x2 %0, %1, %2, %3;" : "=l"(d) : "l"(a), "l"(b), "l"(c));
    return d;
}

__device__ __forceinline__ unsigned long long add2(unsigned long long a,
                                                   unsigned long long b) {
    unsigned long long d;
    asm("add.rn.f32x2 %0, %1, %2;" : "=l"(d) : "l"(a), "l"(b));
    return d;
}

__device__ __forceinline__ unsigned long long pack2(float lo, float hi) {
    unsigned long long r;
    asm("mov.b64 %0, {%1, %2};" : "=l"(r) : "f"(lo), "f"(hi));
    return r;
}

__device__ __forceinline__ void unpack2(unsigned long long v, float& lo, float& hi) {
    asm("mov.b64 {%0, %1}, %2;" : "=f"(lo), "=f"(hi) : "l"(v));
}

__global__ __launch_bounds__(128, 1)
void sync_head_kernel(const float* __restrict__ z_ticks,
                      const float* __restrict__ proj,
                      const float* __restrict__ ln_w,
                      const float* __restrict__ ln_b,
                      const float* __restrict__ cls_w,
                      const float* __restrict__ cls_b,
                      float* __restrict__ out_x,
                      float* __restrict__ out_logits) {
    __shared__ __align__(16) float sZ[2][4][DD];
    __shared__ float4 cst[TT];      // (pad, alpha*inv_denom/128, (1-alpha)*inv_denom, inv_s)
    __shared__ float itab[TT + 1];  // 1/(t+1)
    __shared__ __align__(16) float A[DOUTN][CCLS];   // ln_w[j]*cls_w[c][j]
    __shared__ float4 SaV, SbV;     // folded sums
    __shared__ float xbuf[4][DOUTN * XPITCH];        // per-warp x transpose tile

    const int lane  = threadIdx.x & 31;
    const int w     = threadIdx.x >> 5;
    const int batch = blockIdx.x * 4 + w;

    // ---- per-t constant tables (pure functions of t; parallel fill) ----
    for (int t = threadIdx.x; t <= TT; t += 128) {
        float tau = (float)(t + 1);
        itab[t] = 1.0f / tau;
        if (t < TT) {
            float denom = fmaxf(tau - 1.0f, 1.0f);
            float inv_denom = 1.0f / denom;
            float g = __powf(GAMMA_C, tau);
            float s = (1.0f - g) / (1.0f - GAMMA_C);
            cst[t] = make_float4(0.0f,
                                 ALPHA_C * inv_denom * (1.0f / 128.0f),
                                 (1.0f - ALPHA_C) * inv_denom,
                                 1.0f / s);
        }
    }
    // ---- folded LN x classifier matrix + sums ----
    if (threadIdx.x < DOUTN * CCLS) {
        int j = threadIdx.x >> 2, c = threadIdx.x & 3;
        A[j][c] = ln_w[j] * cls_w[c * DOUTN + j];
    }
    if (threadIdx.x < 2 * CCLS) {
        int c = threadIdx.x & 3;
        float acc = 0.f;
        if (threadIdx.x < CCLS) {
            for (int j = 0; j < DOUTN; j++) acc += ln_w[j] * cls_w[c * DOUTN + j];
            ((float*)&SaV)[c] = acc;
        } else {
            for (int j = 0; j < DOUTN; j++) acc += ln_b[j] * cls_w[c * DOUTN + j];
            ((float*)&SbV)[c] = acc + cls_b[c];
        }
    }

    // ---- proj column `lane` in registers, packed for f32x2 FMA ----
    unsigned long long q[DD / 2];
#pragma unroll
    for (int i = 0; i < DD / 2; i++) {
        float a = proj[(2 * i) * DOUTN + lane];
        float b = proj[(2 * i + 1) * DOUTN + lane];
        q[i] = pack2(a, b);
    }

    __syncthreads();   // tables ready
    const float4 Sa4 = SaV;
    const float4 Sb4 = SbV;

    const float* zptr = z_ticks + (size_t)batch * TT * DD + lane * 4;
    float* ox  = out_x + ((size_t)batch * TT) * DOUTN + lane;
    float* olb = out_logits + ((size_t)batch * TT) * CCLS;
    float* xb  = xbuf[w];

    // ---- preamble: absorb step 0's Welford (m = z0, e = 0, s = 0, b = 0) ----
    float4 z0 = *(const float4*)(zptr);
    float m0 = z0.x, m1 = z0.y, m2_ = z0.z, m3 = z0.w;
    float s0 = 0.f, s1 = 0.f, s2 = 0.f, s3 = 0.f;
    float e0 = 0.f, e1 = 0.f, e2 = 0.f, e3 = 0.f;
    float b = 0.f;        // reduced msum for current step
    float h = 0.f;

    float4 zb0 = *(const float4*)(zptr + DD);        // z_{t+1}
    float4 zb1 = *(const float4*)(zptr + 2 * DD);    // z_{t+2}

#pragma unroll 1
    for (int t = 0; t < TT; t++) {
        const float4 C = cst[t];

        // ---- z_tilde for step t ----
        const float c2 = fmaf(b, C.y, EPS_C);
        const float zt0 = e0 * rsqrtf(fmaf(s0, C.z, c2));
        const float zt1 = e1 * rsqrtf(fmaf(s1, C.z, c2));
        const float zt2 = e2 * rsqrtf(fmaf(s2, C.z, c2));
        const float zt3 = e3 * rsqrtf(fmaf(s3, C.z, c2));

        float* sb = sZ[t & 1][w];
        ((float4*)sb)[lane] = make_float4(zt0, zt1, zt2, zt3);
        __syncwarp();

        // ---- Welford for step t+1 (independent of step t's matvec) ----
        const float4 z = zb0;
        zb0 = zb1;
        {
            int tp = t + 3; if (tp > TT - 1) tp = TT - 1;
            zb1 = *(const float4*)(zptr + (size_t)tp * DD);
        }
        const float itn = itab[t + 1];
        float d0 = z.x - m0, d1 = z.y - m1, d2 = z.z - m2_, d3 = z.w - m3;
        m0 = fmaf(d0, itn, m0);
        m1 = fmaf(d1, itn, m1);
        m2_ = fmaf(d2, itn, m2_);
        m3 = fmaf(d3, itn, m3);
        e0 = z.x - m0; e1 = z.y - m1; e2 = z.z - m2_; e3 = z.w - m3;
        s0 = fmaf(d0, e0, s0);
        s1 = fmaf(d1, e1, s1);
        s2 = fmaf(d2, e2, s2);
        s3 = fmaf(d3, e3, s3);
        // v-bar butterfly for step t+1 (overlaps the matvec below)
        const float bn = warp_sum((s0 + s1) + (s2 + s3));

        // ---- matvec: r[lane] = sum_d z_tilde[d] * proj[d][lane] ----
        const ulonglong2* zp = (const ulonglong2*)sb;
        unsigned long long acc0 = 0ull, acc1 = 0ull, acc2 = 0ull, acc3 = 0ull;
#pragma unroll
        for (int c = 0; c < 16; c++) {
            ulonglong2 za = zp[2 * c];
            ulonglong2 zc = zp[2 * c + 1];
            acc0 = fma2(za.x, q[4 * c + 0], acc0);
            acc1 = fma2(za.y, q[4 * c + 1], acc1);
            acc2 = fma2(zc.x, q[4 * c + 2], acc2);
            acc3 = fma2(zc.y, q[4 * c + 3], acc3);
        }
        b = bn;

        unsigned long long sAB = add2(acc0, acc1);
        unsigned long long sCD = add2(acc2, acc3);
        unsigned long long sT  = add2(sAB, sCD);
        float rlo, rhi;
        unpack2(sT, rlo, rhi);
        const float r = rlo + rhi;

        // ---- h EMA, log feature ----
        h = fmaf(r, r, GAMMA_C * h);
        const float xv = __logf(fmaf(h, C.w, EPSH_C));
        ox[(size_t)t * DOUTN] = xv;
        xb[lane * XPITCH + (t & (TBLK - 1))] = xv;   // transpose buffer (conflict-free)

        // ---- deferred LN+classifier epilogue, once per 32 steps ----
        if ((t & (TBLK - 1)) == (TBLK - 1)) {
            __syncwarp();   // xbuf writes from all lanes visible
            const int tbase = t - (TBLK - 1);
            // lane handles timestep tbase+lane entirely in-register
            float sx = 0.f, sx2 = 0.f;
            float dt0 = 0.f, dt1 = 0.f, dt2 = 0.f, dt3 = 0.f;
#pragma unroll
            for (int j = 0; j < DOUTN; j++) {
                const float xj = xb[j * XPITCH + lane];
                const float4 Aj = *(const float4*)&A[j][0];   // broadcast LDS.128
                sx  += xj;
                sx2 = fmaf(xj, xj, sx2);
                dt0 = fmaf(xj, Aj.x, dt0);
                dt1 = fmaf(xj, Aj.y, dt1);
                dt2 = fmaf(xj, Aj.z, dt2);
                dt3 = fmaf(xj, Aj.w, dt3);
            }
            const float mu      = sx * (1.0f / 32.0f);
            // clamp: serial-summation rounding can drive the analytically
            // nonnegative variance slightly negative (degenerate rows, e.g.
            // t=0 where all features are identical) -> rsqrt(neg) = NaN.
            const float var     = fmaxf(fmaf(sx2, 1.0f / 32.0f, -mu * mu), 0.0f);
            const float inv_std = rsqrtf(var + LNEPS_C);
            float4 lg;
            lg.x = fmaf(inv_std, fmaf(-mu, Sa4.x, dt0), Sb4.x);
            lg.y = fmaf(inv_std, fmaf(-mu, Sa4.y, dt1), Sb4.y);
            lg.z = fmaf(inv_std, fmaf(-mu, Sa4.z, dt2), Sb4.z);
            lg.w = fmaf(inv_std, fmaf(-mu, Sa4.w, dt3), Sb4.w);
            ((float4*)olb)[tbase + lane] = lg;               // coalesced STG.128
            __syncwarp();   // buffer safe to overwrite next step
        }
    }
}

extern "C" void kernel_launch(void* const* d_in, const int* in_sizes, int n_in,
                              void* d_out, int out_size) {
    const float* z_ticks = (const float*)d_in[0];
    const float* proj    = (const float*)d_in[1];
    const float* ln_w    = (const float*)d_in[2];
    const float* ln_b    = (const float*)d_in[3];
    const float* cls_w   = (const float*)d_in[4];
    const float* cls_b   = (const float*)d_in[5];

    float* out_x      = (float*)d_out;
    float* out_logits = out_x + (size_t)BATCH * TT * DOUTN;

    sync_head_kernel<<<BATCH / 4, 128>>>(z_ticks, proj, ln_w, ln_b,
                                         cls_w, cls_b, out_x, out_logits);
}

// round 8
// speedup vs baseline: 1.3042x; 1.1925x over previous
#include <cuda_runtime.h>
#include <cstddef>

#define BATCH 512
#define TT    512
#define DD    128
#define DOUTN 32
#define CCLS  4
#define TBLK  32
#define XPITCH 33

#define ALPHA_C 0.1f
#define GAMMA_C 0.9f
#define EPS_C   1e-5f
#define EPSH_C  1e-6f
#define LNEPS_C 1e-5f

__device__ __forceinline__ float warp_sum(float v) {
#pragma unroll
    for (int s = 16; s > 0; s >>= 1)
        v += __shfl_xor_sync(0xffffffffu, v, s, 32);
    return v;
}

__device__ __forceinline__ unsigned long long fma2(unsigned long long a,
                                                   unsigned long long b,
                                                   unsigned long long c) {
    unsigned long long d;
    asm("fma.rn.f32x2 %0, %1, %2, %3;" : "=l"(d) : "l"(a), "l"(b), "l"(c));
    return d;
}

__device__ __forceinline__ unsigned long long add2(unsigned long long a,
                                                   unsigned long long b) {
    unsigned long long d;
    asm("add.rn.f32x2 %0, %1, %2;" : "=l"(d) : "l"(a), "l"(b));
    return d;
}

__device__ __forceinline__ unsigned long long pack2(float lo, float hi) {
    unsigned long long r;
    asm("mov.b64 %0, {%1, %2};" : "=l"(r) : "f"(lo), "f"(hi));
    return r;
}

__device__ __forceinline__ void unpack2(unsigned long long v, float& lo, float& hi) {
    asm("mov.b64 {%0, %1}, %2;" : "=f"(lo), "=f"(hi) : "l"(v));
}

__global__ __launch_bounds__(128, 1)
void sync_head_kernel(const float* __restrict__ z_ticks,
                      const float* __restrict__ proj,
                      const float* __restrict__ ln_w,
                      const float* __restrict__ ln_b,
                      const float* __restrict__ cls_w,
                      const float* __restrict__ cls_b,
                      float* __restrict__ out_x,
                      float* __restrict__ out_logits) {
    __shared__ __align__(16) float sZ[2][4][DD];
    __shared__ float4 cst[TT];      // (pad, alpha*inv_denom/128, (1-alpha)*inv_denom, inv_s)
    __shared__ float itab[TT + 1];  // 1/(t+1)
    __shared__ __align__(16) float A[DOUTN][CCLS];
    __shared__ float4 SaV, SbV;
    __shared__ float xbuf[4][DOUTN * XPITCH];

    const int lane  = threadIdx.x & 31;
    const int w     = threadIdx.x >> 5;
    const int batch = blockIdx.x * 4 + w;

    for (int t = threadIdx.x; t <= TT; t += 128) {
        float tau = (float)(t + 1);
        itab[t] = 1.0f / tau;
        if (t < TT) {
            float denom = fmaxf(tau - 1.0f, 1.0f);
            float inv_denom = 1.0f / denom;
            float g = __powf(GAMMA_C, tau);
            float s = (1.0f - g) / (1.0f - GAMMA_C);
            cst[t] = make_float4(0.0f,
                                 ALPHA_C * inv_denom * (1.0f / 128.0f),
                                 (1.0f - ALPHA_C) * inv_denom,
                                 1.0f / s);
        }
    }
    if (threadIdx.x < DOUTN * CCLS) {
        int j = threadIdx.x >> 2, c = threadIdx.x & 3;
        A[j][c] = ln_w[j] * cls_w[c * DOUTN + j];
    }
    if (threadIdx.x < 2 * CCLS) {
        int c = threadIdx.x & 3;
        float acc = 0.f;
        if (threadIdx.x < CCLS) {
            for (int j = 0; j < DOUTN; j++) acc += ln_w[j] * cls_w[c * DOUTN + j];
            ((float*)&SaV)[c] = acc;
        } else {
            for (int j = 0; j < DOUTN; j++) acc += ln_b[j] * cls_w[c * DOUTN + j];
            ((float*)&SbV)[c] = acc + cls_b[c];
        }
    }

    unsigned long long q[DD / 2];
#pragma unroll
    for (int i = 0; i < DD / 2; i++) {
        float a = proj[(2 * i) * DOUTN + lane];
        float b = proj[(2 * i + 1) * DOUTN + lane];
        q[i] = pack2(a, b);
    }

    __syncthreads();
    const float4 Sa4 = SaV;
    const float4 Sb4 = SbV;

    const float* zptr = z_ticks + (size_t)batch * TT * DD + lane * 4;
    float* ox  = out_x + ((size_t)batch * TT) * DOUTN + lane;
    float* olb = out_logits + ((size_t)batch * TT) * CCLS;
    float* xb  = xbuf[w];

    // ---- preamble: state after step 0 (m = z0, s = 0); z_tilde_0 = 0 ----
    float4 z0 = *(const float4*)(zptr);
    float m0 = z0.x, m1 = z0.y, m2_ = z0.z, m3 = z0.w;
    float s0 = 0.f, s1 = 0.f, s2 = 0.f, s3 = 0.f;
    float h = 0.f;
    float cw = cst[0].w;       // inv_s for current step, carried

    ((float4*)sZ[0][w])[lane] = make_float4(0.f, 0.f, 0.f, 0.f);
    __syncwarp();

    float4 zb0 = *(const float4*)(zptr + DD);        // z_{t+1}
    float4 zb1 = *(const float4*)(zptr + 2 * DD);    // z_{t+2}

#pragma unroll 2
    for (int t = 0; t < TT; t++) {
        // ---- Welford for step t+1 ----
        const float4 z = zb0;
        zb0 = zb1;
        {
            int tp = t + 3; if (tp > TT - 1) tp = TT - 1;
            zb1 = *(const float4*)(zptr + (size_t)tp * DD);
        }
        const float itn = itab[t + 1];
        float d0 = z.x - m0, d1 = z.y - m1, d2 = z.z - m2_, d3 = z.w - m3;
        // e = z - m_new = d*(1 - itn), independent of the m update
        float e0 = fmaf(-d0, itn, d0);
        float e1 = fmaf(-d1, itn, d1);
        float e2 = fmaf(-d2, itn, d2);
        float e3 = fmaf(-d3, itn, d3);
        m0 = fmaf(d0, itn, m0);
        m1 = fmaf(d1, itn, m1);
        m2_ = fmaf(d2, itn, m2_);
        m3 = fmaf(d3, itn, m3);
        s0 = fmaf(d0, e0, s0);
        s1 = fmaf(d1, e1, s1);
        s2 = fmaf(d2, e2, s2);
        s3 = fmaf(d3, e3, s3);
        // v-bar butterfly for step t+1 (overlaps matvec below)
        const float bn = warp_sum((s0 + s1) + (s2 + s3));

        // ---- matvec for step t (reads z_tilde_t from sZ[t&1]) ----
        const ulonglong2* zp = (const ulonglong2*)sZ[t & 1][w];
        unsigned long long acc0 = 0ull, acc1 = 0ull, acc2 = 0ull, acc3 = 0ull;
#pragma unroll
        for (int c = 0; c < 16; c++) {
            ulonglong2 za = zp[2 * c];
            ulonglong2 zc = zp[2 * c + 1];
            acc0 = fma2(za.x, q[4 * c + 0], acc0);
            acc1 = fma2(za.y, q[4 * c + 1], acc1);
            acc2 = fma2(zc.x, q[4 * c + 2], acc2);
            acc3 = fma2(zc.y, q[4 * c + 3], acc3);
        }
        unsigned long long sAB = add2(acc0, acc1);
        unsigned long long sCD = add2(acc2, acc3);
        unsigned long long sT  = add2(sAB, sCD);
        float rlo, rhi;
        unpack2(sT, rlo, rhi);
        const float r = rlo + rhi;

        // ---- h EMA, log feature for step t ----
        h = fmaf(r, r, GAMMA_C * h);
        const float xv = __logf(fmaf(h, cw, EPSH_C));
        ox[(size_t)t * DOUTN] = xv;
        xb[lane * XPITCH + (t & (TBLK - 1))] = xv;

        // ---- deferred LN+classifier epilogue (every 32 steps) ----
        if ((t & (TBLK - 1)) == (TBLK - 1)) {
            __syncwarp();
            const int tbase = t - (TBLK - 1);
            float sx = 0.f, sx2 = 0.f;
            float dt0 = 0.f, dt1 = 0.f, dt2 = 0.f, dt3 = 0.f;
#pragma unroll
            for (int j = 0; j < DOUTN; j++) {
                const float xj = xb[j * XPITCH + lane];
                const float4 Aj = *(const float4*)&A[j][0];
                sx  += xj;
                sx2 = fmaf(xj, xj, sx2);
                dt0 = fmaf(xj, Aj.x, dt0);
                dt1 = fmaf(xj, Aj.y, dt1);
                dt2 = fmaf(xj, Aj.z, dt2);
                dt3 = fmaf(xj, Aj.w, dt3);
            }
            const float mu      = sx * (1.0f / 32.0f);
            const float var     = fmaxf(fmaf(sx2, 1.0f / 32.0f, -mu * mu), 0.0f);
            const float inv_std = rsqrtf(var + LNEPS_C);
            float4 lg;
            lg.x = fmaf(inv_std, fmaf(-mu, Sa4.x, dt0), Sb4.x);
            lg.y = fmaf(inv_std, fmaf(-mu, Sa4.y, dt1), Sb4.y);
            lg.z = fmaf(inv_std, fmaf(-mu, Sa4.z, dt2), Sb4.z);
            lg.w = fmaf(inv_std, fmaf(-mu, Sa4.w, dt3), Sb4.w);
            ((float4*)olb)[tbase + lane] = lg;
            // no second syncwarp: the end-of-body syncwarp below orders
            // the xbuf WAR against next iteration's writes.
        }

        // ---- produce z_tilde for step t+1 (overlaps log/store tail) ----
        {
            int tn = t + 1; if (tn > TT - 1) tn = TT - 1;
            const float4 C = cst[tn];
            cw = C.w;
            const float c2 = fmaf(bn, C.y, EPS_C);
            const float zt0 = e0 * rsqrtf(fmaf(s0, C.z, c2));
            const float zt1 = e1 * rsqrtf(fmaf(s1, C.z, c2));
            const float zt2 = e2 * rsqrtf(fmaf(s2, C.z, c2));
            const float zt3 = e3 * rsqrtf(fmaf(s3, C.z, c2));
            ((float4*)sZ[(t + 1) & 1][w])[lane] = make_float4(zt0, zt1, zt2, zt3);
            __syncwarp();
        }
    }
}

extern "C" void kernel_launch(void* const* d_in, const int* in_sizes, int n_in,
                              void* d_out, int out_size) {
    const float* z_ticks = (const float*)d_in[0];
    const float* proj    = (const float*)d_in[1];
    const float* ln_w    = (const float*)d_in[2];
    const float* ln_b    = (const float*)d_in[3];
    const float* cls_w   = (const float*)d_in[4];
    const float* cls_b   = (const float*)d_in[5];

    float* out_x      = (float*)d_out;
    float* out_logits = out_x + (size_t)BATCH * TT * DOUTN;

    sync_head_kernel<<<BATCH / 4, 128>>>(z_ticks, proj, ln_w, ln_b,
                                         cls_w, cls_b, out_x, out_logits);
}